// round 10
// baseline (speedup 1.0000x reference)
#include <cuda_runtime.h>
#include <cuda_fp16.h>
#include <cstdint>

#define BATCH 32
#define HH 512
#define WW 512
#define NPX (BATCH * HH * WW)

#define TX 64   // output tile width
#define TY 32   // output tile height
#define SW 72   // smem tile width  (TX + 8)
#define SH2 40  // smem tile height (TY + 8)
#define NT 4    // tiles per CTA (vertical), pipelined via cp.async

// 9x9 kernel weights in constant bank
__constant__ float c_w[81];

// Scratch (device globals: allocation-free per harness rules)
__device__ __half g_lm[NPX];   // local mean, fp16
__device__ __half g_s2[NPX];   // channel-mean squared-dev, fp16
__device__ __half g_sig[NPX];  // sigma, fp16
__device__ float  g_part[BATCH * 128];

typedef unsigned long long u64;

// --- f32x2 packed-math helpers (Blackwell FFMA2 path) ----------------------
__device__ __forceinline__ u64 bcast2(float w) {
    u64 r;
    asm("mov.b64 %0, {%1, %1};" : "=l"(r) : "r"(__float_as_uint(w)));
    return r;
}
__device__ __forceinline__ void fma2(u64& acc, u64 a, u64 b) {
    asm("fma.rn.f32x2 %0, %1, %2, %0;" : "+l"(acc) : "l"(a), "l"(b));
}
// {lo = hi32(a), hi = lo32(b)} : odd-tap pair from two aligned pairs (MOVs)
__device__ __forceinline__ u64 pair_merge(u64 a, u64 b) {
    u64 r;
    asm("mov.b64 %0, {%1, %2};"
        : "=l"(r) : "r"((uint32_t)(a >> 32)), "r"((uint32_t)b));
    return r;
}

// --- cp.async helpers ------------------------------------------------------
__device__ __forceinline__ void cpa16(uint32_t dst, const void* src) {
    uint64_t g;
    asm("cvta.to.global.u64 %0, %1;" : "=l"(g) : "l"(src));
    asm volatile("cp.async.cg.shared.global [%0], [%1], 16;"
                 :: "r"(dst), "l"(g));
}
__device__ __forceinline__ void cpa8(uint32_t dst, const void* src) {
    uint64_t g;
    asm("cvta.to.global.u64 %0, %1;" : "=l"(g) : "l"(src));
    asm volatile("cp.async.ca.shared.global [%0], [%1], 8;"
                 :: "r"(dst), "l"(g));
}
__device__ __forceinline__ void cpa_commit() {
    asm volatile("cp.async.commit_group;");
}
__device__ __forceinline__ void cpa_wait0() {
    asm volatile("cp.async.wait_group 0;" ::: "memory");
}

// ---------------------------------------------------------------------------
// Blur core (double-pair register scheme): thread = 2 cols x 4 rows.
// 60 conflict-free LDS.64/thread; odd taps via register merge.
// ---------------------------------------------------------------------------
__device__ __forceinline__ void blur4(const float* sm, int tx, int tz,
                                      u64 acc[4]) {
#pragma unroll
    for (int i = 0; i < 4; i++) acc[i] = 0ull;

    const u64* b64 = (const u64*)sm + 2 * tz * SW + tx;

    u64 cur0[12], cur1[12];
#pragma unroll
    for (int j = 0; j < 12; j++) cur0[j] = b64[j * (SW / 2)];

#pragma unroll
    for (int p = 0; p < 4; p++) {
#pragma unroll
        for (int ky = 0; ky < 9; ky++) {
            u64 we = bcast2(c_w[ky * 9 + 2 * p]);
#pragma unroll
            for (int oy = 0; oy < 4; oy++) fma2(acc[oy], we, cur0[ky + oy]);
        }
#pragma unroll
        for (int j = 0; j < 12; j++) cur1[j] = b64[j * (SW / 2) + p + 1];
#pragma unroll
        for (int j = 0; j < 12; j++) cur0[j] = pair_merge(cur0[j], cur1[j]);
#pragma unroll
        for (int ky = 0; ky < 9; ky++) {
            u64 wo = bcast2(c_w[ky * 9 + 2 * p + 1]);
#pragma unroll
            for (int oy = 0; oy < 4; oy++) fma2(acc[oy], wo, cur0[ky + oy]);
        }
#pragma unroll
        for (int j = 0; j < 12; j++) cur0[j] = cur1[j];
    }
#pragma unroll
    for (int ky = 0; ky < 9; ky++) {
        u64 we = bcast2(c_w[ky * 9 + 8]);
#pragma unroll
        for (int oy = 0; oy < 4; oy++) fma2(acc[oy], we, cur0[ky + oy]);
    }
}

// ---------------------------------------------------------------------------
// Stage 1 (pipelined): per CTA, NT=4 vertical tiles. Raw x for tile t+1 is
// cp.async-staged (40 rows x 72 px x 12B = 34.6 KB) while tile t blurs.
// smem = 17.3 KB (m f32 + q fp16) + 34.6 KB staging = 51.8 KB -> 4 CTA/SM.
// ---------------------------------------------------------------------------
__global__ __launch_bounds__(256, 4) void k_stage1(const float* __restrict__ x) {
    extern __shared__ float dsm[];
    float*  sm   = dsm;                          // [40][72] f32 (11520 B)
    __half* sq   = (__half*)(dsm + 2880);        // [40][72] fp16 (5760 B)
    float*  stag = dsm + 4320;                   // [40][216] raw x (34560 B)

    const int b = blockIdx.z;
    const int x0 = blockIdx.x * TX;
    const int xleft = x0 - 4;
    const int tid = threadIdx.y * 32 + threadIdx.x;
    const float inv3 = 1.f / 3.f;
    const uint32_t stg = (uint32_t)__cvta_generic_to_shared(stag);

    // ---- stage_load(t): 40 rows x 54 16B-chunks = 2160 chunks -------------
    auto stage_load = [&](int t) {
        int y0 = (blockIdx.y * NT + t) * TY;
        int r = tid / 54, c = tid - r * 54;
        for (int ch = tid; ch < 2160; ch += 256) {
            int gy = y0 - 4 + r;
            int px = xleft + 4 * (c / 3);  // 3 chunks per 4-px group
            uint32_t dst = stg + r * 864 + c * 16;
            if (((unsigned)gy < HH) & ((unsigned)px < WW)) {
                const float* src =
                    x + ((size_t)(b * HH + gy) * WW + xleft) * 3 + c * 4;
                cpa16(dst, src);
            } else {
                asm volatile("st.shared.v4.b32 [%0], {%1,%1,%1,%1};"
                             :: "r"(dst), "r"(0));
            }
            c += 40; r += 4;
            if (c >= 54) { c -= 54; r += 1; }  // 256 = 4*54 + 40
        }
        cpa_commit();
    };

    stage_load(0);
    cpa_wait0();
    __syncthreads();

    const int tx = threadIdx.x, tz = threadIdx.y;

    for (int t = 0; t < NT; t++) {
        const int y0 = (blockIdx.y * NT + t) * TY;

        // ---- m/q compute from staging (720 4-px groups) -------------------
        {
            int r = tid / 18, c = tid - r * 18;
            for (int g = tid; g < 720; g += 256) {
                const float4* sp = (const float4*)(stag + r * 216 + c * 12);
                float4 A = sp[0], B = sp[1], C = sp[2];
                float m0 = (A.x + A.y + A.z) * inv3;
                float m1 = (A.w + B.x + B.y) * inv3;
                float m2 = (B.z + B.w + C.x) * inv3;
                float m3 = (C.y + C.z + C.w) * inv3;
                float q0 = fmaf(A.x, A.x, fmaf(A.y, A.y, A.z * A.z)) * inv3;
                float q1 = fmaf(A.w, A.w, fmaf(B.x, B.x, B.y * B.y)) * inv3;
                float q2 = fmaf(B.z, B.z, fmaf(B.w, B.w, C.x * C.x)) * inv3;
                float q3 = fmaf(C.y, C.y, fmaf(C.z, C.z, C.w * C.w)) * inv3;
                int i = r * SW + 4 * c;
                *(float4*)&sm[i] = make_float4(m0, m1, m2, m3);
                __half2 qa = __floats2half2_rn(q0, q1);
                __half2 qb = __floats2half2_rn(q2, q3);
                *(uint2*)&sq[i] = make_uint2(*(uint32_t*)&qa, *(uint32_t*)&qb);
                c += 4; r += 14;
                if (c >= 18) { c -= 18; r += 1; }  // 256 = 14*18 + 4
            }
        }
        __syncthreads();  // tiles ready; staging fully consumed

        if (t + 1 < NT) stage_load(t + 1);  // async: overlaps the blur below

        u64 acc[4];
        blur4(sm, tx, tz, acc);

#pragma unroll
        for (int oy = 0; oy < 4; oy++) {
            float lm0 = __uint_as_float((uint32_t)acc[oy]);
            float lm1 = __uint_as_float((uint32_t)(acc[oy] >> 32));
            int si = (4 * tz + oy + 4) * SW + 2 * tx + 4;
            float2 mm = *(const float2*)&sm[si];
            float2 qq = __half22float2(*(const __half2*)&sq[si]);
            float s20 = fmaxf(fmaf(lm0, fmaf(-2.f, mm.x, lm0), qq.x), 0.f);
            float s21 = fmaxf(fmaf(lm1, fmaf(-2.f, mm.y, lm1), qq.y), 0.f);
            int idx = (b * HH + y0 + 4 * tz + oy) * WW + x0 + 2 * tx;
            __stcs((__half2*)&g_lm[idx], __floats2half2_rn(lm0, lm1));
            __stcs((__half2*)&g_s2[idx], __floats2half2_rn(s20, s21));
        }

        if (t + 1 < NT) cpa_wait0();
        __syncthreads();  // staging(t+1) visible; mq tile free to overwrite
    }
}

// ---------------------------------------------------------------------------
// Stage 2 (pipelined): same pattern; staging = raw fp16 s2 (40x72x2B=5.8 KB).
// ---------------------------------------------------------------------------
__global__ __launch_bounds__(256, 4) void k_stage2() {
    __shared__ __align__(16) float  ss[2880];
    __shared__ __align__(16) __half stg2a[2880];
    __shared__ float warpsum[8];

    const int b = blockIdx.z;
    const int x0 = blockIdx.x * TX;
    const int xleft = x0 - 4;
    const int tid = threadIdx.y * 32 + threadIdx.x;
    const uint32_t stg = (uint32_t)__cvta_generic_to_shared(stg2a);

    // ---- stage_load(t): 40 rows x 18 8B-chunks = 720 chunks ---------------
    auto stage_load = [&](int t) {
        int y0 = (blockIdx.y * NT + t) * TY;
        int r = tid / 18, c = tid - r * 18;
        for (int ch = tid; ch < 720; ch += 256) {
            int gy = y0 - 4 + r;
            int px = xleft + 4 * c;
            uint32_t dst = stg + r * 144 + c * 8;
            if (((unsigned)gy < HH) & ((unsigned)px < WW)) {
                const __half* src = g_s2 + (size_t)(b * HH + gy) * WW + px;
                cpa8(dst, src);
            } else {
                asm volatile("st.shared.v2.b32 [%0], {%1,%1};"
                             :: "r"(dst), "r"(0));
            }
            c += 4; r += 14;
            if (c >= 18) { c -= 18; r += 1; }
        }
        cpa_commit();
    };

    stage_load(0);
    cpa_wait0();
    __syncthreads();

    const int tx = threadIdx.x, tz = threadIdx.y;

    for (int t = 0; t < NT; t++) {
        const int y0 = (blockIdx.y * NT + t) * TY;

        // ---- expand fp16 staging -> f32 tile ------------------------------
        {
            int r = tid / 18, c = tid - r * 18;
            for (int g = tid; g < 720; g += 256) {
                uint2 u = *(const uint2*)((const char*)stg2a + r * 144 + c * 8);
                float2 a = __half22float2(*(__half2*)&u.x);
                float2 d = __half22float2(*(__half2*)&u.y);
                int i = r * SW + 4 * c;
                *(float4*)&ss[i] = make_float4(a.x, a.y, d.x, d.y);
                c += 4; r += 14;
                if (c >= 18) { c -= 18; r += 1; }
            }
        }
        __syncthreads();

        if (t + 1 < NT) stage_load(t + 1);

        u64 acc[4];
        blur4(ss, tx, tz, acc);

        float lsum = 0.f;
#pragma unroll
        for (int oy = 0; oy < 4; oy++) {
            float s0 = sqrtf(fmaxf(__uint_as_float((uint32_t)acc[oy]), 0.f));
            float s1 = sqrtf(fmaxf(__uint_as_float((uint32_t)(acc[oy] >> 32)), 0.f));
            int idx = (b * HH + y0 + 4 * tz + oy) * WW + x0 + 2 * tx;
            __stcs((__half2*)&g_sig[idx], __floats2half2_rn(s0, s1));
            lsum += s0 + s1;
        }

#pragma unroll
        for (int o = 16; o > 0; o >>= 1)
            lsum += __shfl_down_sync(0xFFFFFFFFu, lsum, o);
        if (tx == 0) warpsum[tz] = lsum;
        __syncthreads();
        if (tid == 0) {
            float s = 0.f;
#pragma unroll
            for (int i = 0; i < 8; i++) s += warpsum[i];
            g_part[b * 128 + (blockIdx.y * NT + t) * 8 + blockIdx.x] = s;
        }

        if (t + 1 < NT) cpa_wait0();
        __syncthreads();
    }
}

// ---------------------------------------------------------------------------
// Final: prologue re-reduces this batch's 128 partials (L2 hits) -> ms, then
// out = (x - lm) / max(ms, sigma). 8 px / thread, streaming float4 traffic.
// ---------------------------------------------------------------------------
__global__ __launch_bounds__(256) void k_final(const float* __restrict__ x,
                                               float* __restrict__ out) {
    __shared__ float s_w[4];
    __shared__ float s_ms;

    const int b = blockIdx.x >> 7;  // 128 blocks / batch
    if (threadIdx.x < 128) {
        float v = g_part[b * 128 + threadIdx.x];
#pragma unroll
        for (int o = 16; o > 0; o >>= 1)
            v += __shfl_down_sync(0xFFFFFFFFu, v, o);
        if ((threadIdx.x & 31) == 0) s_w[threadIdx.x >> 5] = v;
    }
    __syncthreads();
    if (threadIdx.x == 0)
        s_ms = (s_w[0] + s_w[1] + s_w[2] + s_w[3]) *
               (1.f / ((float)HH * (float)WW));
    __syncthreads();
    const float ms = s_ms;

    const int p = (blockIdx.x & 127) * 2048 + threadIdx.x * 8 + (b << 18);

    uint4 lmu = __ldcs((const uint4*)((const __half*)g_lm + p));
    uint4 sgu = __ldcs((const uint4*)((const __half*)g_sig + p));
    const __half2* lmh = (const __half2*)&lmu;
    const __half2* sgh = (const __half2*)&sgu;

    const float4* xp = (const float4*)(x + (size_t)p * 3);
    float4 xv[6];
#pragma unroll
    for (int i = 0; i < 6; i++) xv[i] = __ldcs(xp + i);

    float lmv[8], inv[8];
#pragma unroll
    for (int i = 0; i < 4; i++) {
        float2 l = __half22float2(lmh[i]);
        float2 s = __half22float2(sgh[i]);
        lmv[2 * i] = l.x;
        lmv[2 * i + 1] = l.y;
        inv[2 * i] = __frcp_rn(fmaxf(ms, s.x));
        inv[2 * i + 1] = __frcp_rn(fmaxf(ms, s.y));
    }

    const float* f = (const float*)xv;
    float4* op = (float4*)(out + (size_t)p * 3);
#pragma unroll
    for (int i = 0; i < 6; i++) {
        float o0 = (f[4 * i + 0] - lmv[(4 * i + 0) / 3]) * inv[(4 * i + 0) / 3];
        float o1 = (f[4 * i + 1] - lmv[(4 * i + 1) / 3]) * inv[(4 * i + 1) / 3];
        float o2 = (f[4 * i + 2] - lmv[(4 * i + 2) / 3]) * inv[(4 * i + 2) / 3];
        float o3 = (f[4 * i + 3] - lmv[(4 * i + 3) / 3]) * inv[(4 * i + 3) / 3];
        __stcs(op + i, make_float4(o0, o1, o2, o3));
    }
}

// ---------------------------------------------------------------------------
extern "C" void kernel_launch(void* const* d_in, const int* in_sizes, int n_in,
                              void* d_out, int out_size) {
    const float* x = (const float*)d_in[0];

    cudaMemcpyToSymbolAsync(c_w, d_in[1], 81 * sizeof(float), 0,
                            cudaMemcpyDeviceToDevice, 0);

    const int smem1 = 11520 + 5760 + 34560;  // 51840 B
    cudaFuncSetAttribute(k_stage1, cudaFuncAttributeMaxDynamicSharedMemorySize,
                         smem1);

    dim3 blk(32, 8);
    dim3 grd(WW / TX, HH / (TY * NT), BATCH);  // (8, 4, 32) = 1024 CTAs
    k_stage1<<<grd, blk, smem1>>>(x);
    k_stage2<<<grd, blk>>>();
    k_final<<<BATCH * 128, 256>>>(x, (float*)d_out);
}